// round 13
// baseline (speedup 1.0000x reference)
#include <cuda_runtime.h>
#include <cuda_fp16.h>
#include <mma.h>
#include <math.h>

using namespace nvcuda;

#define LL   9216
#define DI   192
#define DS   16
#define DR   6
#define KK   4
#define XD   38
#define NB   2
#define NSEG 192
#define CH   48
#define HH   96
#define WW   96
#define TLC  128
#define GRP  16
#define SEGPG (NSEG/GRP)

// ---------------- scratch ----------------
__device__ __half g_xi   [NB*LL*DI];
__device__ __half g_z    [NB*LL*DI];
__device__ __half g_xc   [NB*LL*DI];
__device__ __half g_delta[NB*KK*LL*DI];
__device__ __half g_y    [NB*KK*LL*DI];
__device__ float  g_bc   [NB*KK*LL*32];
__device__ float  g_S    [NB*KK*NSEG*DS*DI];
__device__ float  g_dsm  [NB*KK*NSEG*DI];
__device__ float  g_h0   [NB*KK*NSEG*DS*DI];
__device__ float  g_Sg   [NB*KK*GRP*DS*DI];
__device__ float  g_dsmg [NB*KK*GRP*DI];
__device__ float  g_h0g  [NB*KK*GRP*DS*DI];
__device__ __half g_ipw_h[384*96];
__device__ __half g_xpw_h[KK*48*DI];
__device__ __half g_opw_h[96*200];

__constant__ float c_logn[DS] = {
    0.0f, 0.69314718f, 1.09861229f, 1.38629436f,
    1.60943791f, 1.79175947f, 1.94591015f, 2.07944154f,
    2.19722458f, 2.30258509f, 2.39789527f, 2.48490665f,
    2.56494936f, 2.63905733f, 2.70805020f, 2.77258872f
};

__device__ __forceinline__ float softplus_exact(float x){
    return fmaxf(x, 0.f) + __logf(1.f + __expf(-fabsf(x)));
}
__device__ __forceinline__ int pos_of(int k, int i){
    int t = (k >= 2) ? (LL - 1 - i) : i;
    if (k & 1){ int h = t % HH; int w = t / HH; return h*WW + w; }
    return t;
}
__device__ __forceinline__ bool row_fast(const float* arow){
    float a0 = arow[0];
    bool fast = true;
    #pragma unroll
    for (int n = 1; n < DS; n++)
        fast = fast && (fabsf(arow[n] - a0 - c_logn[n]) <= 2e-5f);
    return fast;
}
__device__ __forceinline__ int pstride_of(int k){
    return (k==0) ? 1 : (k==1) ? WW : (k==2) ? -1 : -WW;
}

// fast exp for small args: 4-term Taylor, warp-voted exact fallback
#define FAST_E1(v_, e1) { \
    e1 = 1.f + (v_)*(1.f + (v_)*(0.5f + (v_)*(0.16666667f + (v_)*0.04166667f))); \
    if (__any_sync(0xffffffffu, fabsf(v_) >= 0.25f)){ \
        if (fabsf(v_) >= 0.25f) e1 = __expf(v_); \
    } \
}

// ---------------- kernel W: one-time fp16 weight conversion ----------------
__global__ void kW(const float* __restrict__ ipw, const float* __restrict__ xpw,
                   const float* __restrict__ opw){
    int t = blockIdx.x*256 + threadIdx.x;
    if (t < 384*96) g_ipw_h[t] = __float2half_rn(ipw[t]);
    if (t < KK*48*DI){
        int k = t / (48*DI);
        int r = t % (48*DI);
        g_xpw_h[t] = (r < XD*DI) ? __float2half_rn(xpw[k*XD*DI + r]) : __float2half_rn(0.f);
    }
    if (t < 96*200){
        int c = t/200, e = t%200;
        g_opw_h[t] = (e < DI) ? __float2half_rn(opw[c*DI + e]) : __float2half_rn(0.f);
    }
}

// ---------------- kernel A: in_proj via wmma, direct fp16 fragment stores ----------------
__global__ void __launch_bounds__(256) kA(const float* __restrict__ x){
    extern __shared__ __align__(16) char smraw[];
    __half* swh = (__half*)smraw;        // [384][96]
    __half* sxh = swh + 384*96;          // [96][64]

    int tid = threadIdx.x;
    int b    = blockIdx.x / 144;
    int l0   = (blockIdx.x % 144) * 64;

    {
        const float4* src = (const float4*)g_ipw_h;
        float4* dst = (float4*)swh;
        for (int i = tid; i < 384*96/8; i += 256) dst[i] = src[i];
    }
    for (int i = tid; i < 96*64; i += 256){
        int e = i >> 6, j = i & 63;
        sxh[e*64 + j] = __float2half_rn(x[(b*96 + e)*LL + l0 + j]);
    }
    __syncthreads();

    int wid = tid >> 5;
    wmma::fragment<wmma::accumulator,16,16,16,float> acc[3][4];
    #pragma unroll
    for (int i = 0; i < 3; i++)
        #pragma unroll
        for (int j = 0; j < 4; j++) wmma::fill_fragment(acc[i][j], 0.f);

    #pragma unroll
    for (int k = 0; k < 96; k += 16){
        wmma::fragment<wmma::matrix_a,16,16,16,__half,wmma::row_major> af[3];
        wmma::fragment<wmma::matrix_b,16,16,16,__half,wmma::row_major> bf[4];
        #pragma unroll
        for (int i = 0; i < 3; i++)
            wmma::load_matrix_sync(af[i], swh + (wid*48 + i*16)*96 + k, 96);
        #pragma unroll
        for (int j = 0; j < 4; j++)
            wmma::load_matrix_sync(bf[j], sxh + k*64 + j*16, 64);
        #pragma unroll
        for (int i = 0; i < 3; i++)
            #pragma unroll
            for (int j = 0; j < 4; j++)
                wmma::mma_sync(acc[i][j], af[i], bf[j], acc[i][j]);
    }

    #pragma unroll
    for (int i = 0; i < 3; i++){
        int orow = wid*48 + i*16;
        #pragma unroll
        for (int j = 0; j < 4; j++){
            wmma::fragment<wmma::accumulator,16,16,16,__half> hf;
            #pragma unroll
            for (int e = 0; e < hf.num_elements; e++)
                hf.x[e] = __float2half_rn(acc[i][j].x[e]);
            __half* dst;
            if (orow < DI) dst = g_xi + ((size_t)(b*LL + l0 + j*16))*DI + orow;
            else           dst = g_z  + ((size_t)(b*LL + l0 + j*16))*DI + (orow - DI);
            wmma::store_matrix_sync(dst, hf, DI, wmma::mem_col_major);
        }
    }
}

// ---------------- kernel B: depthwise 3x3 conv + SiLU ----------------
__global__ void __launch_bounds__(256) kB(const float* __restrict__ cw, const float* __restrict__ cb){
    __shared__ float scwT[9*DI];
    __shared__ float scb[DI];
    for (int i = threadIdx.x; i < DI*9; i += 256){
        int d = i/9, t = i%9; scwT[t*DI + d] = cw[i];
    }
    for (int i = threadIdx.x; i < DI; i += 256) scb[i] = cb[i];
    __syncthreads();

    int idx = blockIdx.x*256 + threadIdx.x;
    if (idx >= NB*96*48*24) return;
    int dg = idx % 24;
    int t  = idx / 24;
    int wp = t % 48;
    int h  = (t / 48) % 96;
    int b  = t / (48*96);
    int d  = dg*8;

    float acc0[8], acc1[8];
    #pragma unroll
    for (int i = 0; i < 8; i++){ acc0[i] = scb[d+i]; acc1[i] = scb[d+i]; }
    int wl = 2*wp - 1;
    bool hasL = (wl >= 0), hasR = (2*wp + 2 < WW);
    float4 zero4 = make_float4(0.f,0.f,0.f,0.f);

    #pragma unroll
    for (int ky = 0; ky < 3; ky++){
        int hh = h + ky - 1; if (hh < 0 || hh >= HH) continue;
        const __half* row = g_xi + ((size_t)b*LL + hh*WW)*DI + d;
        float4 q0 = hasL ? *(const float4*)(row + wl*DI)       : zero4;
        float4 q1 =        *(const float4*)(row + (2*wp)*DI);
        float4 q2 =        *(const float4*)(row + (2*wp+1)*DI);
        float4 q3 = hasR ? *(const float4*)(row + (2*wp+2)*DI) : zero4;
        float f0[8], f1[8], f2[8], f3[8];
        {
            __half2* p0 = (__half2*)&q0; __half2* p1 = (__half2*)&q1;
            __half2* p2 = (__half2*)&q2; __half2* p3 = (__half2*)&q3;
            #pragma unroll
            for (int j = 0; j < 4; j++){
                float2 a = __half22float2(p0[j]); f0[2*j] = a.x; f0[2*j+1] = a.y;
                float2 c = __half22float2(p1[j]); f1[2*j] = c.x; f1[2*j+1] = c.y;
                float2 e = __half22float2(p2[j]); f2[2*j] = e.x; f2[2*j+1] = e.y;
                float2 g = __half22float2(p3[j]); f3[2*j] = g.x; f3[2*j+1] = g.y;
            }
        }
        float wt[3][8];
        #pragma unroll
        for (int tap = 0; tap < 3; tap++){
            float4 a = *(const float4*)(scwT + (ky*3+tap)*DI + d);
            float4 bq = *(const float4*)(scwT + (ky*3+tap)*DI + d + 4);
            wt[tap][0]=a.x; wt[tap][1]=a.y; wt[tap][2]=a.z; wt[tap][3]=a.w;
            wt[tap][4]=bq.x; wt[tap][5]=bq.y; wt[tap][6]=bq.z; wt[tap][7]=bq.w;
        }
        #pragma unroll
        for (int i = 0; i < 8; i++){
            acc0[i] += wt[0][i]*f0[i] + wt[1][i]*f1[i] + wt[2][i]*f2[i];
            acc1[i] += wt[0][i]*f1[i] + wt[1][i]*f2[i] + wt[2][i]*f3[i];
        }
    }
    float4 o0, o1;
    __half2* o0h = (__half2*)&o0; __half2* o1h = (__half2*)&o1;
    #pragma unroll
    for (int j = 0; j < 4; j++){
        float s0a = acc0[2*j]   * (1.f/(1.f+__expf(-acc0[2*j])));
        float s0b = acc0[2*j+1] * (1.f/(1.f+__expf(-acc0[2*j+1])));
        float s1a = acc1[2*j]   * (1.f/(1.f+__expf(-acc1[2*j])));
        float s1b = acc1[2*j+1] * (1.f/(1.f+__expf(-acc1[2*j+1])));
        o0h[j] = __floats2half2_rn(s0a, s0b);
        o1h[j] = __floats2half2_rn(s1a, s1b);
    }
    __half* orow = g_xc + ((size_t)b*LL + h*WW)*DI + d;
    *(float4*)(orow + (2*wp)*DI)   = o0;
    *(float4*)(orow + (2*wp+1)*DI) = o1;
}

// ---------------- kernel C1: x_proj via wmma + dt proj + 1-MUFU softplus ----------------
__global__ void __launch_bounds__(256) kC1(const float* __restrict__ dtw,
                    const float* __restrict__ dtb){
    extern __shared__ __align__(16) char smraw[];
    __half* swph = (__half*)smraw;            // [48][192]
    __half* sxh  = swph + 48*DI;              // [128][192]
    float*  sdw  = (float*)(sxh + TLC*DI);    // [192][9]
    float*  sdb  = sdw + DI*9;                // [192]
    int*    spos = (int*)(sdb + DI);          // [128]
    float*  sxd  = (float*)smraw;             // overlay: [128][48]
    int tid = threadIdx.x;
    int tile   = blockIdx.x;
    int ntile  = LL / TLC;
    int g  = tile / ntile;
    int i0 = (tile % ntile) * TLC;
    int b = g / KK, k = g % KK;

    {
        const float4* src = (const float4*)(g_xpw_h + k*48*DI);
        float4* dst = (float4*)swph;
        for (int i = tid; i < 48*DI/8; i += 256) dst[i] = src[i];
    }
    for (int i = tid; i < DI*DR; i += 256){
        int d = i/DR, r = i%DR; sdw[d*9 + r] = dtw[k*DI*DR + i];
    }
    for (int i = tid; i < DI; i += 256) sdb[i] = dtb[k*DI + i];
    if (tid < TLC) spos[tid] = pos_of(k, i0 + tid);
    __syncthreads();

    for (int i = tid; i < TLC*96; i += 256){
        int j = i / 96, dd = i % 96;
        *(__half2*)(sxh + j*DI + 2*dd) =
            *(const __half2*)(g_xc + ((size_t)(b*LL + spos[j]))*DI + 2*dd);
    }
    __syncthreads();

    int wid = tid >> 5;
    wmma::fragment<wmma::accumulator,16,16,16,float> acc[3];
    #pragma unroll
    for (int i = 0; i < 3; i++) wmma::fill_fragment(acc[i], 0.f);
    #pragma unroll
    for (int k0 = 0; k0 < DI; k0 += 16){
        wmma::fragment<wmma::matrix_a,16,16,16,__half,wmma::row_major> af;
        wmma::fragment<wmma::matrix_b,16,16,16,__half,wmma::col_major> bf;
        wmma::load_matrix_sync(bf, sxh + (wid*16)*DI + k0, DI);
        #pragma unroll
        for (int i = 0; i < 3; i++){
            wmma::load_matrix_sync(af, swph + (i*16)*DI + k0, DI);
            wmma::mma_sync(acc[i], af, bf, acc[i]);
        }
    }
    __syncthreads();
    #pragma unroll
    for (int i = 0; i < 3; i++)
        wmma::store_matrix_sync(sxd + (wid*16)*48 + i*16, acc[i], 48, wmma::mem_col_major);
    __syncthreads();

    for (int o = tid; o < TLC*32; o += 256){
        int j = o >> 5, c = o & 31;
        g_bc[((size_t)g*LL + i0 + j)*32 + c] = sxd[j*48 + 6 + c];
    }
    // delta epilogue: 1-MUFU softplus (poly log1p for x < -1.6, voted exact fallback)
    {
        int d = (tid < DI) ? tid : tid - DI;
        int j = (tid < DI) ? 0 : 1;
        __half* dbase = g_delta + ((size_t)g*LL + i0)*DI;
        #pragma unroll 4
        for (int it = 0; it < TLC*DI/256; it++){
            const float* xd = sxd + j*48;
            const float* dw = sdw + d*9;
            float acc2 = sdb[d];
            #pragma unroll
            for (int r = 0; r < DR; r++) acc2 += xd[r]*dw[r];
            float t = __expf(acc2);
            float dl = t*(1.f - t*(0.5f - t*(0.33333333f - t*(0.25f - t*0.2f))));
            if (__any_sync(0xffffffffu, acc2 >= -1.6f)){
                if (acc2 >= -1.6f) dl = softplus_exact(acc2);
            }
            dbase[(size_t)j*DI + d] = __float2half_rn(dl);
            d += 64;
            if (d >= DI){ d -= DI; j += 2; } else j += 1;
        }
    }
}

// scan step body (fast path): poly exp + grouped power chain
#define STEP_BODY_D1(s2, delta, u) { \
    dsum += (delta); \
    float du = (delta)*(u); \
    float v_ = (delta)*Ar0; \
    float e1; FAST_E1(v_, e1); \
    float e2 = e1*e1, e4 = e2*e2, e8 = e4*e4, e12 = e8*e4; \
    const float4* Bp4 = (const float4*)(sB + (s2)*DS); \
    float4 B0=Bp4[0],B1=Bp4[1],B2=Bp4[2],B3=Bp4[3]; \
    float aq = e1; \
    h[0]=aq*h[0]+du*B0.x; aq*=e1; h[1]=aq*h[1]+du*B0.y; aq*=e1; h[2]=aq*h[2]+du*B0.z; aq*=e1; h[3]=aq*h[3]+du*B0.w; \
    float bq = e4*e1; \
    h[4]=bq*h[4]+du*B1.x; bq*=e1; h[5]=bq*h[5]+du*B1.y; bq*=e1; h[6]=bq*h[6]+du*B1.z; bq*=e1; h[7]=bq*h[7]+du*B1.w; \
    float cq = e8*e1; \
    h[8]=cq*h[8]+du*B2.x; cq*=e1; h[9]=cq*h[9]+du*B2.y; cq*=e1; h[10]=cq*h[10]+du*B2.z; cq*=e1; h[11]=cq*h[11]+du*B2.w; \
    float dq = e12*e1; \
    h[12]=dq*h[12]+du*B3.x; dq*=e1; h[13]=dq*h[13]+du*B3.y; dq*=e1; h[14]=dq*h[14]+du*B3.z; dq*=e1; h[15]=dq*h[15]+du*B3.w; \
}

// ---------------- kernel D1: per-segment partial scan ----------------
__global__ void __launch_bounds__(192) kD1(const float* __restrict__ A_logs){
    __shared__ float sB[CH*DS];
    int g   = blockIdx.x / NSEG;
    int seg = blockIdx.x % NSEG;
    int b = g / KK, k = g % KK;
    int d = threadIdx.x;
    int l0 = seg * CH;

    for (int i = threadIdx.x; i < CH*DS; i += 192){
        int ss = i >> 4, c = i & 15;
        sB[i] = g_bc[((size_t)g*LL + l0 + ss)*32 + c];
    }
    __syncthreads();

    const float* arow = A_logs + (k*DI + d)*DS;
    bool fast = row_fast(arow);
    float Ar0 = -expf(arow[0]);

    float h[DS];
    #pragma unroll
    for (int n = 0; n < DS; n++) h[n] = 0.f;
    float dsum = 0.f;

    int p0   = pos_of(k, l0);
    int pstr = pstride_of(k) * DI;
    const __half* dptr = g_delta + ((size_t)g*LL + l0)*DI + d;
    const __half* uptr = g_xc + ((size_t)b*LL + p0)*DI + d;

    if (fast){
        for (int c0 = 0; c0 < CH; c0 += 4){
            float dl[4], uu[4];
            #pragma unroll
            for (int j = 0; j < 4; j++){
                dl[j] = __half2float(dptr[(c0+j)*DI]);
                uu[j] = __half2float(uptr[(c0+j)*pstr]);
            }
            #pragma unroll
            for (int j = 0; j < 4; j++){
                STEP_BODY_D1(c0+j, dl[j], uu[j]);
            }
        }
    } else {
        float Ar[DS];
        #pragma unroll
        for (int n = 0; n < DS; n++) Ar[n] = -expf(arow[n]);
        for (int s2 = 0; s2 < CH; s2++){
            float delta = __half2float(dptr[s2*DI]);
            float u = __half2float(uptr[s2*pstr]);
            dsum += delta;
            float du = delta*u;
            const float* Bp = sB + s2*DS;
            #pragma unroll
            for (int n = 0; n < DS; n++){
                float e = __expf(delta*Ar[n]);
                h[n] = e*h[n] + du*Bp[n];
            }
        }
    }
    size_t sbase = (((size_t)g*NSEG + seg)*DS)*DI + d;
    #pragma unroll
    for (int n = 0; n < DS; n++) g_S[sbase + n*DI] = h[n];
    g_dsm[((size_t)g*NSEG + seg)*DI + d] = dsum;
}

// ---------------- kernel D2a: per-group partial ----------------
__global__ void kD2a(const float* __restrict__ A_logs){
    int t = blockIdx.x*blockDim.x + threadIdx.x;
    if (t >= NB*KK*GRP*DS*DI) return;
    int d   = t % DI;
    int n   = (t/DI) % DS;
    int grp = (t/(DI*DS)) % GRP;
    int g   = t/(DI*DS*GRP);
    int k = g % KK;
    float An = -expf(A_logs[(k*DI + d)*DS + n]);
    float h = 0.f, dtot = 0.f;
    size_t base0 = (size_t)g*NSEG + grp*SEGPG;
    for (int s = 0; s < SEGPG; s++){
        size_t base = base0 + s;
        float dsm = g_dsm[base*DI + d];
        h = __expf(An*dsm)*h + g_S[(base*DS + n)*DI + d];
        dtot += dsm;
    }
    size_t gb = (size_t)g*GRP + grp;
    g_Sg[(gb*DS + n)*DI + d] = h;
    if (n == 0) g_dsmg[gb*DI + d] = dtot;
}

// ---------------- kernel D2b: scan 16 groups serially ----------------
__global__ void kD2b(const float* __restrict__ A_logs){
    int t = blockIdx.x*blockDim.x + threadIdx.x;
    if (t >= NB*KK*DS*DI) return;
    int d = t % DI; int n = (t/DI) % DS; int g = t/(DI*DS);
    int k = g % KK;
    float An = -expf(A_logs[(k*DI + d)*DS + n]);
    float h = 0.f;
    for (int grp = 0; grp < GRP; grp++){
        size_t gb = (size_t)g*GRP + grp;
        g_h0g[(gb*DS + n)*DI + d] = h;
        h = __expf(An*g_dsmg[gb*DI + d])*h + g_Sg[(gb*DS + n)*DI + d];
    }
}

// ---------------- kernel D2c: within-group h0 emit ----------------
__global__ void kD2c(const float* __restrict__ A_logs){
    int t = blockIdx.x*blockDim.x + threadIdx.x;
    if (t >= NB*KK*GRP*DS*DI) return;
    int d   = t % DI;
    int n   = (t/DI) % DS;
    int grp = (t/(DI*DS)) % GRP;
    int g   = t/(DI*DS*GRP);
    int k = g % KK;
    float An = -expf(A_logs[(k*DI + d)*DS + n]);
    size_t gb = (size_t)g*GRP + grp;
    float h = g_h0g[(gb*DS + n)*DI + d];
    size_t base0 = (size_t)g*NSEG + grp*SEGPG;
    for (int s = 0; s < SEGPG; s++){
        size_t base = base0 + s;
        g_h0[(base*DS + n)*DI + d] = h;
        h = __expf(An*g_dsm[base*DI + d])*h + g_S[(base*DS + n)*DI + d];
    }
}

#define STEP_BODY_D3(s2, delta, u) { \
    float du = (delta)*(u); \
    float v_ = (delta)*Ar0; \
    float e1; FAST_E1(v_, e1); \
    float e2 = e1*e1, e4 = e2*e2, e8 = e4*e4, e12 = e8*e4; \
    const float4* P4 = (const float4*)(sBC + (s2)*32); \
    float4 B0=P4[0],B1=P4[1],B2=P4[2],B3=P4[3]; \
    float4 C0=P4[4],C1=P4[5],C2=P4[6],C3=P4[7]; \
    float y = 0.f; \
    float aq = e1; \
    h[0]=aq*h[0]+du*B0.x; y+=h[0]*C0.x; aq*=e1; h[1]=aq*h[1]+du*B0.y; y+=h[1]*C0.y; aq*=e1; \
    h[2]=aq*h[2]+du*B0.z; y+=h[2]*C0.z; aq*=e1; h[3]=aq*h[3]+du*B0.w; y+=h[3]*C0.w; \
    float bq = e4*e1; \
    h[4]=bq*h[4]+du*B1.x; y+=h[4]*C1.x; bq*=e1; h[5]=bq*h[5]+du*B1.y; y+=h[5]*C1.y; bq*=e1; \
    h[6]=bq*h[6]+du*B1.z; y+=h[6]*C1.z; bq*=e1; h[7]=bq*h[7]+du*B1.w; y+=h[7]*C1.w; \
    float cq = e8*e1; \
    h[8]=cq*h[8]+du*B2.x; y+=h[8]*C2.x; cq*=e1; h[9]=cq*h[9]+du*B2.y; y+=h[9]*C2.y; cq*=e1; \
    h[10]=cq*h[10]+du*B2.z; y+=h[10]*C2.z; cq*=e1; h[11]=cq*h[11]+du*B2.w; y+=h[11]*C2.w; \
    float dq = e12*e1; \
    h[12]=dq*h[12]+du*B3.x; y+=h[12]*C3.x; dq*=e1; h[13]=dq*h[13]+du*B3.y; y+=h[13]*C3.y; dq*=e1; \
    h[14]=dq*h[14]+du*B3.z; y+=h[14]*C3.z; dq*=e1; h[15]=dq*h[15]+du*B3.w; y+=h[15]*C3.w; \
    yptr[(s2)*DI] = __float2half_rn(y + Dval*(u)); \
}

// ---------------- kernel D3: full scan, emit y ----------------
__global__ void __launch_bounds__(192) kD3(const float* __restrict__ A_logs,
                                           const float* __restrict__ Dsv){
    __shared__ float sBC[CH*32];
    int g   = blockIdx.x / NSEG;
    int seg = blockIdx.x % NSEG;
    int b = g / KK, k = g % KK;
    int d = threadIdx.x;
    int l0 = seg * CH;

    {
        const float4* src = (const float4*)(g_bc + ((size_t)g*LL + l0)*32);
        float4* dst = (float4*)sBC;
        for (int i = threadIdx.x; i < CH*8; i += 192) dst[i] = src[i];
    }
    __syncthreads();

    const float* arow = A_logs + (k*DI + d)*DS;
    bool fast = row_fast(arow);
    float Ar0 = -expf(arow[0]);

    float h[DS];
    size_t hbase = (((size_t)g*NSEG + seg)*DS)*DI + d;
    #pragma unroll
    for (int n = 0; n < DS; n++) h[n] = g_h0[hbase + n*DI];
    float Dval = Dsv[k*DI + d];

    int p0   = pos_of(k, l0);
    int pstr = pstride_of(k) * DI;
    const __half* dptr = g_delta + ((size_t)g*LL + l0)*DI + d;
    const __half* uptr = g_xc + ((size_t)b*LL + p0)*DI + d;
    __half* yptr = g_y + ((size_t)g*LL + l0)*DI + d;

    if (fast){
        for (int c0 = 0; c0 < CH; c0 += 4){
            float dl[4], uu[4];
            #pragma unroll
            for (int j = 0; j < 4; j++){
                dl[j] = __half2float(dptr[(c0+j)*DI]);
                uu[j] = __half2float(uptr[(c0+j)*pstr]);
            }
            #pragma unroll
            for (int j = 0; j < 4; j++){
                STEP_BODY_D3(c0+j, dl[j], uu[j]);
            }
        }
    } else {
        float Ar[DS];
        #pragma unroll
        for (int n = 0; n < DS; n++) Ar[n] = -expf(arow[n]);
        for (int s2 = 0; s2 < CH; s2++){
            float delta = __half2float(dptr[s2*DI]);
            float u = __half2float(uptr[s2*pstr]);
            float du = delta*u;
            const float* Bp = sBC + s2*32;
            const float* Cp = Bp + 16;
            float y = 0.f;
            #pragma unroll
            for (int n = 0; n < DS; n++){
                float e = __expf(delta*Ar[n]);
                h[n] = e*h[n] + du*Bp[n];
                y += h[n]*Cp[n];
            }
            yptr[s2*DI] = __float2half_rn(y + Dval*u);
        }
    }
}

// ---------------- kernel E: merge + LN + gate + wmma out_proj + residual ----------------
__global__ void __launch_bounds__(256) kE(const float* __restrict__ lng,
                                          const float* __restrict__ lnb,
                                          const float* __restrict__ x,
                                          float* __restrict__ out){
    extern __shared__ __align__(16) char smraw[];
    __half* swh  = (__half*)smraw;           // [96][200]
    __half* syoh = swh + 96*200;             // [64][200]
    float*  slg  = (float*)(syoh + 64*200);  // [192]
    float*  slb  = slg + DI;                 // [192]
    float*  sout = (float*)syoh;             // reused after GEMM: [96][64]

    int tid = threadIdx.x;
    int b  = blockIdx.x / (LL/64);
    int p0 = (blockIdx.x % (LL/64)) * 64;

    {
        const float4* src = (const float4*)g_opw_h;
        float4* dst = (float4*)swh;
        for (int i = tid; i < 96*200/8; i += 256) dst[i] = src[i];
    }
    for (int i = tid; i < DI; i += 256){ slg[i] = lng[i]; slb[i] = lnb[i]; }
    for (int i = tid; i < 64*4; i += 256){
        int j = i/4, e = 192 + (i%4)*2;
        *(__half2*)(syoh + j*200 + e) = __floats2half2_rn(0.f, 0.f);
    }
    __syncthreads();

    int lane = tid & 31, wrp = tid >> 5;

    for (int jj = 0; jj < 8; jj++){
        int j = wrp*8 + jj;
        int p = p0 + j;
        int ph = p / WW, pw = p % WW;
        int i1 = pw*HH + ph;
        float val[6];
        #pragma unroll
        for (int i = 0; i < 6; i++){
            int d = lane + 32*i;
            val[i] = __half2float(g_y[(((size_t)(b*KK + 0))*LL + p)*DI + d])
                   + __half2float(g_y[(((size_t)(b*KK + 2))*LL + (LL-1-p))*DI + d])
                   + __half2float(g_y[(((size_t)(b*KK + 1))*LL + i1)*DI + d])
                   + __half2float(g_y[(((size_t)(b*KK + 3))*LL + (LL-1-i1))*DI + d]);
        }
        float s1 = 0.f, s2 = 0.f;
        #pragma unroll
        for (int i = 0; i < 6; i++){ s1 += val[i]; s2 += val[i]*val[i]; }
        #pragma unroll
        for (int off = 16; off; off >>= 1){
            s1 += __shfl_xor_sync(0xffffffffu, s1, off);
            s2 += __shfl_xor_sync(0xffffffffu, s2, off);
        }
        float mu  = s1 * (1.f/192.f);
        float var = s2 * (1.f/192.f) - mu*mu;
        float inv = rsqrtf(var + 1e-5f);
        #pragma unroll
        for (int i = 0; i < 6; i++){
            int d = lane + 32*i;
            float yo = (val[i] - mu)*inv*slg[d] + slb[d];
            float zv = __half2float(g_z[((size_t)b*LL + p)*DI + d]);
            yo *= zv * (1.f / (1.f + __expf(-zv)));
            syoh[j*200 + d] = __float2half_rn(yo);
        }
    }
    __syncthreads();

    wmma::fragment<wmma::accumulator,16,16,16,float> acc[4];
    int wid = tid >> 5;
    if (wid < 6){
        #pragma unroll
        for (int j = 0; j < 4; j++) wmma::fill_fragment(acc[j], 0.f);
        #pragma unroll
        for (int k0 = 0; k0 < DI; k0 += 16){
            wmma::fragment<wmma::matrix_a,16,16,16,__half,wmma::row_major> af;
            wmma::load_matrix_sync(af, swh + (wid*16)*200 + k0, 200);
            #pragma unroll
            for (int j = 0; j < 4; j++){
                wmma::fragment<wmma::matrix_b,16,16,16,__half,wmma::col_major> bf;
                wmma::load_matrix_sync(bf, syoh + (j*16)*200 + k0, 200);
                wmma::mma_sync(acc[j], af, bf, acc[j]);
            }
        }
    }
    __syncthreads();
    if (wid < 6){
        #pragma unroll
        for (int j = 0; j < 4; j++)
            wmma::store_matrix_sync(sout + (wid*16)*64 + j*16, acc[j], 64, wmma::mem_row_major);
    }
    __syncthreads();
    for (int idx = tid; idx < 96*64; idx += 256){
        int c = idx >> 6, jx = idx & 63;
        size_t go = ((size_t)b*96 + c)*LL + p0 + jx;
        out[go] = sout[idx] + x[go];
    }
}

// ---------------- launch ----------------
extern "C" void kernel_launch(void* const* d_in, const int* in_sizes, int n_in,
                              void* d_out, int out_size){
    const float* x    = (const float*)d_in[0];
    const float* ipw  = (const float*)d_in[1];
    const float* cw   = (const float*)d_in[2];
    const float* cb   = (const float*)d_in[3];
    const float* xpw  = (const float*)d_in[4];
    const float* dtw  = (const float*)d_in[5];
    const float* dtb  = (const float*)d_in[6];
    const float* alog = (const float*)d_in[7];
    const float* Dsv  = (const float*)d_in[8];
    const float* lng  = (const float*)d_in[9];
    const float* lnb  = (const float*)d_in[10];
    const float* opw  = (const float*)d_in[11];
    float* out = (float*)d_out;

    int smA = (384*96 + 96*64)*2;
    int smC = (48*DI + TLC*DI)*2 + (DI*9 + DI + TLC)*4;
    int smE = (96*200 + 64*200)*2 + (DI + DI)*4;
    cudaFuncSetAttribute(kA,  cudaFuncAttributeMaxDynamicSharedMemorySize, smA);
    cudaFuncSetAttribute(kC1, cudaFuncAttributeMaxDynamicSharedMemorySize, smC);
    cudaFuncSetAttribute(kE,  cudaFuncAttributeMaxDynamicSharedMemorySize, smE);

    kW<<<(384*96 + 255)/256, 256>>>(ipw, xpw, opw);
    kA<<<NB*144, 256, smA>>>(x);
    int nbB = (NB*96*48*24 + 255)/256;
    kB<<<nbB, 256>>>(cw, cb);
    kC1<<<NB*KK*(LL/TLC), 256, smC>>>(dtw, dtb);
    kD1<<<NB*KK*NSEG, 192>>>(alog);
    int nGrpT = NB*KK*GRP*DS*DI;
    kD2a<<<(nGrpT + 255)/256, 256>>>(alog);
    kD2b<<<(NB*KK*DS*DI + 255)/256, 256>>>(alog);
    kD2c<<<(nGrpT + 255)/256, 256>>>(alog);
    kD3<<<NB*KK*NSEG, 192>>>(alog, Dsv);
    kE<<<NB*(LL/64), 256, smE>>>(lng, lnb, x, out);
}

// round 14
// speedup vs baseline: 1.0054x; 1.0054x over previous
#include <cuda_runtime.h>
#include <cuda_fp16.h>
#include <mma.h>
#include <math.h>

using namespace nvcuda;

#define LL   9216
#define DI   192
#define DS   16
#define DR   6
#define KK   4
#define XD   38
#define NB   2
#define NSEG 192
#define CH   48
#define HH   96
#define WW   96
#define TLC  128
#define GRP  16
#define SEGPG (NSEG/GRP)
#define PXB  64

// ---------------- scratch ----------------
__device__ __half g_xi   [NB*LL*DI];
__device__ __half g_z    [NB*LL*DI];
__device__ __half g_xc   [NB*LL*DI];
__device__ __half g_delta[NB*KK*LL*DI];
__device__ __half g_y    [NB*KK*LL*DI];
__device__ float  g_bc   [NB*KK*LL*32];
__device__ float  g_dt6  [NB*KK*LL*8];
__device__ float  g_S    [NB*KK*NSEG*DS*DI];
__device__ float  g_dsm  [NB*KK*NSEG*DI];
__device__ float  g_h0   [NB*KK*NSEG*DS*DI];
__device__ float  g_Sg   [NB*KK*GRP*DS*DI];
__device__ float  g_dsmg [NB*KK*GRP*DI];
__device__ float  g_h0g  [NB*KK*GRP*DS*DI];
__device__ __half g_ipw_h[384*96];
__device__ __half g_xpw_h[KK*48*DI];
__device__ __half g_opw_h[96*200];

__constant__ float c_logn[DS] = {
    0.0f, 0.69314718f, 1.09861229f, 1.38629436f,
    1.60943791f, 1.79175947f, 1.94591015f, 2.07944154f,
    2.19722458f, 2.30258509f, 2.39789527f, 2.48490665f,
    2.56494936f, 2.63905733f, 2.70805020f, 2.77258872f
};

__device__ __forceinline__ float fast_softplus(float x){
    return fmaxf(x, 0.f) + __logf(1.f + __expf(-fabsf(x)));
}
__device__ __forceinline__ int pos_of(int k, int i){
    int t = (k >= 2) ? (LL - 1 - i) : i;
    if (k & 1){ int h = t % HH; int w = t / HH; return h*WW + w; }
    return t;
}
__device__ __forceinline__ bool row_fast(const float* arow){
    float a0 = arow[0];
    bool fast = true;
    #pragma unroll
    for (int n = 1; n < DS; n++)
        fast = fast && (fabsf(arow[n] - a0 - c_logn[n]) <= 2e-5f);
    return fast;
}
__device__ __forceinline__ int pstride_of(int k){
    return (k==0) ? 1 : (k==1) ? WW : (k==2) ? -1 : -WW;
}

// ---------------- kernel W: one-time fp16 weight conversion ----------------
__global__ void kW(const float* __restrict__ ipw, const float* __restrict__ xpw,
                   const float* __restrict__ opw){
    int t = blockIdx.x*256 + threadIdx.x;
    if (t < 384*96) g_ipw_h[t] = __float2half_rn(ipw[t]);
    if (t < KK*48*DI){
        int k = t / (48*DI);
        int r = t % (48*DI);
        g_xpw_h[t] = (r < XD*DI) ? __float2half_rn(xpw[k*XD*DI + r]) : __float2half_rn(0.f);
    }
    if (t < 96*200){
        int c = t/200, e = t%200;
        g_opw_h[t] = (e < DI) ? __float2half_rn(opw[c*DI + e]) : __float2half_rn(0.f);
    }
}

// ---------------- kernel A: in_proj via wmma, direct fp16 fragment stores ----------------
__global__ void __launch_bounds__(256) kA(const float* __restrict__ x){
    extern __shared__ __align__(16) char smraw[];
    __half* swh = (__half*)smraw;        // [384][96]
    __half* sxh = swh + 384*96;          // [96][64]

    int tid = threadIdx.x;
    int b    = blockIdx.x / 144;
    int l0   = (blockIdx.x % 144) * 64;

    {
        const float4* src = (const float4*)g_ipw_h;
        float4* dst = (float4*)swh;
        for (int i = tid; i < 384*96/8; i += 256) dst[i] = src[i];
    }
    for (int i = tid; i < 96*64; i += 256){
        int e = i >> 6, j = i & 63;
        sxh[e*64 + j] = __float2half_rn(x[(b*96 + e)*LL + l0 + j]);
    }
    __syncthreads();

    int wid = tid >> 5;
    wmma::fragment<wmma::accumulator,16,16,16,float> acc[3][4];
    #pragma unroll
    for (int i = 0; i < 3; i++)
        #pragma unroll
        for (int j = 0; j < 4; j++) wmma::fill_fragment(acc[i][j], 0.f);

    #pragma unroll
    for (int k = 0; k < 96; k += 16){
        wmma::fragment<wmma::matrix_a,16,16,16,__half,wmma::row_major> af[3];
        wmma::fragment<wmma::matrix_b,16,16,16,__half,wmma::row_major> bf[4];
        #pragma unroll
        for (int i = 0; i < 3; i++)
            wmma::load_matrix_sync(af[i], swh + (wid*48 + i*16)*96 + k, 96);
        #pragma unroll
        for (int j = 0; j < 4; j++)
            wmma::load_matrix_sync(bf[j], sxh + k*64 + j*16, 64);
        #pragma unroll
        for (int i = 0; i < 3; i++)
            #pragma unroll
            for (int j = 0; j < 4; j++)
                wmma::mma_sync(acc[i][j], af[i], bf[j], acc[i][j]);
    }

    #pragma unroll
    for (int i = 0; i < 3; i++){
        int orow = wid*48 + i*16;
        #pragma unroll
        for (int j = 0; j < 4; j++){
            wmma::fragment<wmma::accumulator,16,16,16,__half> hf;
            #pragma unroll
            for (int e = 0; e < hf.num_elements; e++)
                hf.x[e] = __float2half_rn(acc[i][j].x[e]);
            __half* dst;
            if (orow < DI) dst = g_xi + ((size_t)(b*LL + l0 + j*16))*DI + orow;
            else           dst = g_z  + ((size_t)(b*LL + l0 + j*16))*DI + (orow - DI);
            wmma::store_matrix_sync(dst, hf, DI, wmma::mem_col_major);
        }
    }
}

// ---------------- kernel B: depthwise 3x3 conv + SiLU ----------------
__global__ void __launch_bounds__(256) kB(const float* __restrict__ cw, const float* __restrict__ cb){
    __shared__ float scwT[9*DI];
    __shared__ float scb[DI];
    for (int i = threadIdx.x; i < DI*9; i += 256){
        int d = i/9, t = i%9; scwT[t*DI + d] = cw[i];
    }
    for (int i = threadIdx.x; i < DI; i += 256) scb[i] = cb[i];
    __syncthreads();

    int idx = blockIdx.x*256 + threadIdx.x;
    if (idx >= NB*96*48*24) return;
    int dg = idx % 24;
    int t  = idx / 24;
    int wp = t % 48;
    int h  = (t / 48) % 96;
    int b  = t / (48*96);
    int d  = dg*8;

    float acc0[8], acc1[8];
    #pragma unroll
    for (int i = 0; i < 8; i++){ acc0[i] = scb[d+i]; acc1[i] = scb[d+i]; }
    int wl = 2*wp - 1;
    bool hasL = (wl >= 0), hasR = (2*wp + 2 < WW);
    float4 zero4 = make_float4(0.f,0.f,0.f,0.f);

    #pragma unroll
    for (int ky = 0; ky < 3; ky++){
        int hh = h + ky - 1; if (hh < 0 || hh >= HH) continue;
        const __half* row = g_xi + ((size_t)b*LL + hh*WW)*DI + d;
        float4 q0 = hasL ? *(const float4*)(row + wl*DI)       : zero4;
        float4 q1 =        *(const float4*)(row + (2*wp)*DI);
        float4 q2 =        *(const float4*)(row + (2*wp+1)*DI);
        float4 q3 = hasR ? *(const float4*)(row + (2*wp+2)*DI) : zero4;
        float f0[8], f1[8], f2[8], f3[8];
        {
            __half2* p0 = (__half2*)&q0; __half2* p1 = (__half2*)&q1;
            __half2* p2 = (__half2*)&q2; __half2* p3 = (__half2*)&q3;
            #pragma unroll
            for (int j = 0; j < 4; j++){
                float2 a = __half22float2(p0[j]); f0[2*j] = a.x; f0[2*j+1] = a.y;
                float2 c = __half22float2(p1[j]); f1[2*j] = c.x; f1[2*j+1] = c.y;
                float2 e = __half22float2(p2[j]); f2[2*j] = e.x; f2[2*j+1] = e.y;
                float2 g = __half22float2(p3[j]); f3[2*j] = g.x; f3[2*j+1] = g.y;
            }
        }
        float wt[3][8];
        #pragma unroll
        for (int tap = 0; tap < 3; tap++){
            float4 a = *(const float4*)(scwT + (ky*3+tap)*DI + d);
            float4 bq = *(const float4*)(scwT + (ky*3+tap)*DI + d + 4);
            wt[tap][0]=a.x; wt[tap][1]=a.y; wt[tap][2]=a.z; wt[tap][3]=a.w;
            wt[tap][4]=bq.x; wt[tap][5]=bq.y; wt[tap][6]=bq.z; wt[tap][7]=bq.w;
        }
        #pragma unroll
        for (int i = 0; i < 8; i++){
            acc0[i] += wt[0][i]*f0[i] + wt[1][i]*f1[i] + wt[2][i]*f2[i];
            acc1[i] += wt[0][i]*f1[i] + wt[1][i]*f2[i] + wt[2][i]*f3[i];
        }
    }
    float4 o0, o1;
    __half2* o0h = (__half2*)&o0; __half2* o1h = (__half2*)&o1;
    #pragma unroll
    for (int j = 0; j < 4; j++){
        float s0a = acc0[2*j]   * (1.f/(1.f+__expf(-acc0[2*j])));
        float s0b = acc0[2*j+1] * (1.f/(1.f+__expf(-acc0[2*j+1])));
        float s1a = acc1[2*j]   * (1.f/(1.f+__expf(-acc1[2*j])));
        float s1b = acc1[2*j+1] * (1.f/(1.f+__expf(-acc1[2*j+1])));
        o0h[j] = __floats2half2_rn(s0a, s0b);
        o1h[j] = __floats2half2_rn(s1a, s1b);
    }
    __half* orow = g_xc + ((size_t)b*LL + h*WW)*DI + d;
    *(float4*)(orow + (2*wp)*DI)   = o0;
    *(float4*)(orow + (2*wp+1)*DI) = o1;
}

// ---------------- kernel C1a: gather + x_proj wmma + write B/C + dt6 ----------------
__global__ void __launch_bounds__(256) kC1a(){
    extern __shared__ __align__(16) char smraw[];
    __half* swph = (__half*)smraw;            // [48][192]
    __half* sxh  = swph + 48*DI;              // [128][192]
    int*    spos = (int*)(sxh + TLC*DI);      // [128]
    float*  sxd  = (float*)smraw;             // overlay: [128][48]
    int tid = threadIdx.x;
    int tile   = blockIdx.x;
    int ntile  = LL / TLC;
    int g  = tile / ntile;
    int i0 = (tile % ntile) * TLC;
    int b = g / KK, k = g % KK;

    {
        const float4* src = (const float4*)(g_xpw_h + k*48*DI);
        float4* dst = (float4*)swph;
        for (int i = tid; i < 48*DI/8; i += 256) dst[i] = src[i];
    }
    if (tid < TLC) spos[tid] = pos_of(k, i0 + tid);
    __syncthreads();

    for (int i = tid; i < TLC*96; i += 256){
        int j = i / 96, dd = i % 96;
        *(__half2*)(sxh + j*DI + 2*dd) =
            *(const __half2*)(g_xc + ((size_t)(b*LL + spos[j]))*DI + 2*dd);
    }
    __syncthreads();

    int wid = tid >> 5;
    wmma::fragment<wmma::accumulator,16,16,16,float> acc[3];
    #pragma unroll
    for (int i = 0; i < 3; i++) wmma::fill_fragment(acc[i], 0.f);
    #pragma unroll
    for (int k0 = 0; k0 < DI; k0 += 16){
        wmma::fragment<wmma::matrix_a,16,16,16,__half,wmma::row_major> af;
        wmma::fragment<wmma::matrix_b,16,16,16,__half,wmma::col_major> bf;
        wmma::load_matrix_sync(bf, sxh + (wid*16)*DI + k0, DI);
        #pragma unroll
        for (int i = 0; i < 3; i++){
            wmma::load_matrix_sync(af, swph + (i*16)*DI + k0, DI);
            wmma::mma_sync(acc[i], af, bf, acc[i]);
        }
    }
    __syncthreads();
    #pragma unroll
    for (int i = 0; i < 3; i++)
        wmma::store_matrix_sync(sxd + (wid*16)*48 + i*16, acc[i], 48, wmma::mem_col_major);
    __syncthreads();

    for (int o = tid; o < TLC*32; o += 256){
        int j = o >> 5, c = o & 31;
        g_bc[((size_t)g*LL + i0 + j)*32 + c] = sxd[j*48 + 6 + c];
    }
    for (int o = tid; o < TLC*8; o += 256){
        int j = o >> 3, r = o & 7;
        g_dt6[((size_t)g*LL + i0 + j)*8 + r] = (r < DR) ? sxd[j*48 + r] : 0.f;
    }
}

// ---------------- kernel C1b: dt proj + softplus, streaming ----------------
__global__ void __launch_bounds__(256) kC1b(const float* __restrict__ dtw,
                                            const float* __restrict__ dtb){
    __shared__ float sdw[DI*9];
    __shared__ float sdb[DI];
    __shared__ float sdt[PXB*8];
    int tid = threadIdx.x;
    int blk = blockIdx.x;
    int ntile = LL / PXB;                // 144
    int g  = blk / ntile;
    int i0 = (blk % ntile) * PXB;
    int k = g % KK;

    for (int i = tid; i < DI*DR; i += 256){
        int d = i/DR, r = i%DR; sdw[d*9 + r] = dtw[k*DI*DR + i];
    }
    for (int i = tid; i < DI; i += 256) sdb[i] = dtb[k*DI + i];
    {
        const float4* src = (const float4*)(g_dt6 + ((size_t)g*LL + i0)*8);
        float4* dst = (float4*)sdt;
        for (int i = tid; i < PXB*2; i += 256) dst[i] = src[i];
    }
    __syncthreads();

    int d = (tid < DI) ? tid : tid - DI;
    int j = (tid < DI) ? 0 : 1;
    __half* dbase = g_delta + ((size_t)g*LL + i0)*DI;
    #pragma unroll 4
    for (int it = 0; it < PXB*DI/256; it++){
        const float* xd = sdt + j*8;
        const float* dw = sdw + d*9;
        float acc2 = sdb[d];
        #pragma unroll
        for (int r = 0; r < DR; r++) acc2 += xd[r]*dw[r];
        dbase[(size_t)j*DI + d] = __float2half_rn(fast_softplus(acc2));
        d += 64;
        if (d >= DI){ d -= DI; j += 2; } else j += 1;
    }
}

// scan step body (fast path): grouped power chain, depth 4
#define STEP_BODY_D1(s2, delta, u) { \
    dsum += (delta); \
    float du = (delta)*(u); \
    float e1 = __expf((delta)*Ar0); \
    float e2 = e1*e1, e4 = e2*e2, e8 = e4*e4, e12 = e8*e4; \
    const float4* Bp4 = (const float4*)(sB + (s2)*DS); \
    float4 B0=Bp4[0],B1=Bp4[1],B2=Bp4[2],B3=Bp4[3]; \
    float aq = e1; \
    h[0]=aq*h[0]+du*B0.x; aq*=e1; h[1]=aq*h[1]+du*B0.y; aq*=e1; h[2]=aq*h[2]+du*B0.z; aq*=e1; h[3]=aq*h[3]+du*B0.w; \
    float bq = e4*e1; \
    h[4]=bq*h[4]+du*B1.x; bq*=e1; h[5]=bq*h[5]+du*B1.y; bq*=e1; h[6]=bq*h[6]+du*B1.z; bq*=e1; h[7]=bq*h[7]+du*B1.w; \
    float cq = e8*e1; \
    h[8]=cq*h[8]+du*B2.x; cq*=e1; h[9]=cq*h[9]+du*B2.y; cq*=e1; h[10]=cq*h[10]+du*B2.z; cq*=e1; h[11]=cq*h[11]+du*B2.w; \
    float dq = e12*e1; \
    h[12]=dq*h[12]+du*B3.x; dq*=e1; h[13]=dq*h[13]+du*B3.y; dq*=e1; h[14]=dq*h[14]+du*B3.z; dq*=e1; h[15]=dq*h[15]+du*B3.w; \
}

// ---------------- kernel D1: per-segment partial scan ----------------
__global__ void __launch_bounds__(192) kD1(const float* __restrict__ A_logs){
    __shared__ float sB[CH*DS];
    int g   = blockIdx.x / NSEG;
    int seg = blockIdx.x % NSEG;
    int b = g / KK, k = g % KK;
    int d = threadIdx.x;
    int l0 = seg * CH;

    for (int i = threadIdx.x; i < CH*DS; i += 192){
        int ss = i >> 4, c = i & 15;
        sB[i] = g_bc[((size_t)g*LL + l0 + ss)*32 + c];
    }
    __syncthreads();

    const float* arow = A_logs + (k*DI + d)*DS;
    bool fast = row_fast(arow);
    float Ar0 = -expf(arow[0]);

    float h[DS];
    #pragma unroll
    for (int n = 0; n < DS; n++) h[n] = 0.f;
    float dsum = 0.f;

    int p0   = pos_of(k, l0);
    int pstr = pstride_of(k) * DI;
    const __half* dptr = g_delta + ((size_t)g*LL + l0)*DI + d;
    const __half* uptr = g_xc + ((size_t)b*LL + p0)*DI + d;

    if (fast){
        for (int c0 = 0; c0 < CH; c0 += 4){
            float dl[4], uu[4];
            #pragma unroll
            for (int j = 0; j < 4; j++){
                dl[j] = __half2float(dptr[(c0+j)*DI]);
                uu[j] = __half2float(uptr[(c0+j)*pstr]);
            }
            #pragma unroll
            for (int j = 0; j < 4; j++){
                STEP_BODY_D1(c0+j, dl[j], uu[j]);
            }
        }
    } else {
        float Ar[DS];
        #pragma unroll
        for (int n = 0; n < DS; n++) Ar[n] = -expf(arow[n]);
        for (int s2 = 0; s2 < CH; s2++){
            float delta = __half2float(dptr[s2*DI]);
            float u = __half2float(uptr[s2*pstr]);
            dsum += delta;
            float du = delta*u;
            const float* Bp = sB + s2*DS;
            #pragma unroll
            for (int n = 0; n < DS; n++){
                float e = __expf(delta*Ar[n]);
                h[n] = e*h[n] + du*Bp[n];
            }
        }
    }
    size_t sbase = (((size_t)g*NSEG + seg)*DS)*DI + d;
    #pragma unroll
    for (int n = 0; n < DS; n++) g_S[sbase + n*DI] = h[n];
    g_dsm[((size_t)g*NSEG + seg)*DI + d] = dsum;
}

// ---------------- kernel D2a: per-group partial ----------------
__global__ void kD2a(const float* __restrict__ A_logs){
    int t = blockIdx.x*blockDim.x + threadIdx.x;
    if (t >= NB*KK*GRP*DS*DI) return;
    int d   = t % DI;
    int n   = (t/DI) % DS;
    int grp = (t/(DI*DS)) % GRP;
    int g   = t/(DI*DS*GRP);
    int k = g % KK;
    float An = -expf(A_logs[(k*DI + d)*DS + n]);
    float h = 0.f, dtot = 0.f;
    size_t base0 = (size_t)g*NSEG + grp*SEGPG;
    for (int s = 0; s < SEGPG; s++){
        size_t base = base0 + s;
        float dsm = g_dsm[base*DI + d];
        h = __expf(An*dsm)*h + g_S[(base*DS + n)*DI + d];
        dtot += dsm;
    }
    size_t gb = (size_t)g*GRP + grp;
    g_Sg[(gb*DS + n)*DI + d] = h;
    if (n == 0) g_dsmg[gb*DI + d] = dtot;
}

// ---------------- kernel D2b: scan 16 groups serially ----------------
__global__ void kD2b(const float* __restrict__ A_logs){
    int t = blockIdx.x*blockDim.x + threadIdx.x;
    if (t >= NB*KK*DS*DI) return;
    int d = t % DI; int n = (t/DI) % DS; int g = t/(DI*DS);
    int k = g % KK;
    float An = -expf(A_logs[(k*DI + d)*DS + n]);
    float h = 0.f;
    for (int grp = 0; grp < GRP; grp++){
        size_t gb = (size_t)g*GRP + grp;
        g_h0g[(gb*DS + n)*DI + d] = h;
        h = __expf(An*g_dsmg[gb*DI + d])*h + g_Sg[(gb*DS + n)*DI + d];
    }
}

// ---------------- kernel D2c: within-group h0 emit ----------------
__global__ void kD2c(const float* __restrict__ A_logs){
    int t = blockIdx.x*blockDim.x + threadIdx.x;
    if (t >= NB*KK*GRP*DS*DI) return;
    int d   = t % DI;
    int n   = (t/DI) % DS;
    int grp = (t/(DI*DS)) % GRP;
    int g   = t/(DI*DS*GRP);
    int k = g % KK;
    float An = -expf(A_logs[(k*DI + d)*DS + n]);
    size_t gb = (size_t)g*GRP + grp;
    float h = g_h0g[(gb*DS + n)*DI + d];
    size_t base0 = (size_t)g*NSEG + grp*SEGPG;
    for (int s = 0; s < SEGPG; s++){
        size_t base = base0 + s;
        g_h0[(base*DS + n)*DI + d] = h;
        h = __expf(An*g_dsm[base*DI + d])*h + g_S[(base*DS + n)*DI + d];
    }
}

#define STEP_BODY_D3(s2, delta, u) { \
    float du = (delta)*(u); \
    float e1 = __expf((delta)*Ar0); \
    float e2 = e1*e1, e4 = e2*e2, e8 = e4*e4, e12 = e8*e4; \
    const float4* P4 = (const float4*)(sBC + (s2)*32); \
    float4 B0=P4[0],B1=P4[1],B2=P4[2],B3=P4[3]; \
    float4 C0=P4[4],C1=P4[5],C2=P4[6],C3=P4[7]; \
    float y = 0.f; \
    float aq = e1; \
    h[0]=aq*h[0]+du*B0.x; y+=h[0]*C0.x; aq*=e1; h[1]=aq*h[1]+du*B0.y; y+=h[1]*C0.y; aq*=e1; \
    h[2]=aq*h[2]+du*B0.z; y+=h[2]*C0.z; aq*=e1; h[3]=aq*h[3]+du*B0.w; y+=h[3]*C0.w; \
    float bq = e4*e1; \
    h[4]=bq*h[4]+du*B1.x; y+=h[4]*C1.x; bq*=e1; h[5]=bq*h[5]+du*B1.y; y+=h[5]*C1.y; bq*=e1; \
    h[6]=bq*h[6]+du*B1.z; y+=h[6]*C1.z; bq*=e1; h[7]=bq*h[7]+du*B1.w; y+=h[7]*C1.w; \
    float cq = e8*e1; \
    h[8]=cq*h[8]+du*B2.x; y+=h[8]*C2.x; cq*=e1; h[9]=cq*h[9]+du*B2.y; y+=h[9]*C2.y; cq*=e1; \
    h[10]=cq*h[10]+du*B2.z; y+=h[10]*C2.z; cq*=e1; h[11]=cq*h[11]+du*B2.w; y+=h[11]*C2.w; \
    float dq = e12*e1; \
    h[12]=dq*h[12]+du*B3.x; y+=h[12]*C3.x; dq*=e1; h[13]=dq*h[13]+du*B3.y; y+=h[13]*C3.y; dq*=e1; \
    h[14]=dq*h[14]+du*B3.z; y+=h[14]*C3.z; dq*=e1; h[15]=dq*h[15]+du*B3.w; y+=h[15]*C3.w; \
    yptr[(s2)*DI] = __float2half_rn(y + Dval*(u)); \
}

// ---------------- kernel D3: full scan, emit y ----------------
__global__ void __launch_bounds__(192) kD3(const float* __restrict__ A_logs,
                                           const float* __restrict__ Dsv){
    __shared__ float sBC[CH*32];
    int g   = blockIdx.x / NSEG;
    int seg = blockIdx.x % NSEG;
    int b = g / KK, k = g % KK;
    int d = threadIdx.x;
    int l0 = seg * CH;

    {
        const float4* src = (const float4*)(g_bc + ((size_t)g*LL + l0)*32);
        float4* dst = (float4*)sBC;
        for (int i = threadIdx.x; i < CH*8; i += 192) dst[i] = src[i];
    }
    __syncthreads();

    const float* arow = A_logs + (k*DI + d)*DS;
    bool fast = row_fast(arow);
    float Ar0 = -expf(arow[0]);

    float h[DS];
    size_t hbase = (((size_t)g*NSEG + seg)*DS)*DI + d;
    #pragma unroll
    for (int n = 0; n < DS; n++) h[n] = g_h0[hbase + n*DI];
    float Dval = Dsv[k*DI + d];

    int p0   = pos_of(k, l0);
    int pstr = pstride_of(k) * DI;
    const __half* dptr = g_delta + ((size_t)g*LL + l0)*DI + d;
    const __half* uptr = g_xc + ((size_t)b*LL + p0)*DI + d;
    __half* yptr = g_y + ((size_t)g*LL + l0)*DI + d;

    if (fast){
        for (int c0 = 0; c0 < CH; c0 += 4){
            float dl[4], uu[4];
            #pragma unroll
            for (int j = 0; j < 4; j++){
                dl[j] = __half2float(dptr[(c0+j)*DI]);
                uu[j] = __half2float(uptr[(c0+j)*pstr]);
            }
            #pragma unroll
            for (int j = 0; j < 4; j++){
                STEP_BODY_D3(c0+j, dl[j], uu[j]);
            }
        }
    } else {
        float Ar[DS];
        #pragma unroll
        for (int n = 0; n < DS; n++) Ar[n] = -expf(arow[n]);
        for (int s2 = 0; s2 < CH; s2++){
            float delta = __half2float(dptr[s2*DI]);
            float u = __half2float(uptr[s2*pstr]);
            float du = delta*u;
            const float* Bp = sBC + s2*32;
            const float* Cp = Bp + 16;
            float y = 0.f;
            #pragma unroll
            for (int n = 0; n < DS; n++){
                float e = __expf(delta*Ar[n]);
                h[n] = e*h[n] + du*Bp[n];
                y += h[n]*Cp[n];
            }
            yptr[s2*DI] = __float2half_rn(y + Dval*u);
        }
    }
}

// ---------------- kernel E: merge + LN + gate + wmma out_proj + residual ----------------
__global__ void __launch_bounds__(256) kE(const float* __restrict__ lng,
                                          const float* __restrict__ lnb,
                                          const float* __restrict__ x,
                                          float* __restrict__ out){
    extern __shared__ __align__(16) char smraw[];
    __half* swh  = (__half*)smraw;           // [96][200]
    __half* syoh = swh + 96*200;             // [64][200]
    float*  slg  = (float*)(syoh + 64*200);  // [192]
    float*  slb  = slg + DI;                 // [192]
    float*  sout = (float*)syoh;             // reused after GEMM: [96][64]

    int tid = threadIdx.x;
    int b  = blockIdx.x / (LL/64);
    int p0 = (blockIdx.x % (LL/64)) * 64;

    {
        const float4* src = (const float4*)g_opw_h;
        float4* dst = (float4*)swh;
        for (int i = tid; i < 96*200/8; i += 256) dst[i] = src[i];
    }
    for (int i = tid; i < DI; i += 256){ slg[i] = lng[i]; slb[i] = lnb[i]; }
    for (int i = tid; i < 64*4; i += 256){
        int j = i/4, e = 192 + (i%4)*2;
        *(__half2*)(syoh + j*200 + e) = __floats2half2_rn(0.f, 0.f);
    }
    __syncthreads();

    int lane = tid & 31, wrp = tid >> 5;

    for (int jj = 0; jj < 8; jj++){
        int j = wrp*8 + jj;
        int p = p0 + j;
        int ph = p / WW, pw = p % WW;
        int i1 = pw*HH + ph;
        float val[6];
        #pragma unroll
        for (int i = 0; i < 6; i++){
            int d = lane + 32*i;
            val[i] = __half2float(g_y[(((size_t)(b*KK + 0))*LL + p)*DI + d])
                   + __half2float(g_y[(((size_t)(b*KK + 2))*LL + (LL-1-p))*DI + d])
                   + __half2float(g_y[(((size_t)(b*KK + 1))*LL + i1)*DI + d])
                   + __half2float(g_y[(((size_t)(b*KK + 3))*LL + (LL-1-i1))*DI + d]);
        }
        float s1 = 0.f, s2 = 0.f;
        #pragma unroll
        for (int i = 0; i < 6; i++){ s1 += val[i]; s2 += val[i]*val[i]; }
        #pragma unroll
        for (int off = 16; off; off >>= 1){
            s1 += __shfl_xor_sync(0xffffffffu, s1, off);
            s2 += __shfl_xor_sync(0xffffffffu, s2, off);
        }
        float mu  = s1 * (1.f/192.f);
        float var = s2 * (1.f/192.f) - mu*mu;
        float inv = rsqrtf(var + 1e-5f);
        #pragma unroll
        for (int i = 0; i < 6; i++){
            int d = lane + 32*i;
            float yo = (val[i] - mu)*inv*slg[d] + slb[d];
            float zv = __half2float(g_z[((size_t)b*LL + p)*DI + d]);
            yo *= zv * (1.f / (1.f + __expf(-zv)));
            syoh[j*200 + d] = __float2half_rn(yo);
        }
    }
    __syncthreads();

    wmma::fragment<wmma::accumulator,16,16,16,float> acc[4];
    int wid = tid >> 5;
    if (wid < 6){
        #pragma unroll
        for (int j = 0; j < 4; j++) wmma::fill_fragment(acc[j], 0.f);
        #pragma unroll
        for (int k0 = 0; k0 < DI; k0 += 16){
            wmma::fragment<wmma::matrix_a,16,16,16,__half,wmma::row_major> af;
            wmma::load_matrix_sync(af, swh + (wid*16)*200 + k0, 200);
            #pragma unroll
            for (int j = 0; j < 4; j++){
                wmma::fragment<wmma::matrix_b,16,16,16,__half,wmma::col_major> bf;
                wmma::load_matrix_sync(bf, syoh + (j*16)*200 + k0, 200);
                wmma::mma_sync(acc[j], af, bf, acc[j]);
            }
        }
    }
    __syncthreads();
    if (wid < 6){
        #pragma unroll
        for (int j = 0; j < 4; j++)
            wmma::store_matrix_sync(sout + (wid*16)*64 + j*16, acc[j], 64, wmma::mem_row_major);
    }
    __syncthreads();
    for (int idx = tid; idx < 96*64; idx += 256){
        int c = idx >> 6, jx = idx & 63;
        size_t go = ((size_t)b*96 + c)*LL + p0 + jx;
        out[go] = sout[idx] + x[go];
    }
}

// ---------------- launch ----------------
extern "C" void kernel_launch(void* const* d_in, const int* in_sizes, int n_in,
                              void* d_out, int out_size){
    const float* x    = (const float*)d_in[0];
    const float* ipw  = (const float*)d_in[1];
    const float* cw   = (const float*)d_in[2];
    const float* cb   = (const float*)d_in[3];
    const float* xpw  = (const float*)d_in[4];
    const float* dtw  = (const float*)d_in[5];
    const float* dtb  = (const float*)d_in[6];
    const float* alog = (const float*)d_in[7];
    const float* Dsv  = (const float*)d_in[8];
    const float* lng  = (const float*)d_in[9];
    const float* lnb  = (const float*)d_in[10];
    const float* opw  = (const float*)d_in[11];
    float* out = (float*)d_out;

    int smA = (384*96 + 96*64)*2;
    int smC = (48*DI + TLC*DI)*2 + TLC*4;
    int smE = (96*200 + 64*200)*2 + (DI + DI)*4;
    cudaFuncSetAttribute(kA,   cudaFuncAttributeMaxDynamicSharedMemorySize, smA);
    cudaFuncSetAttribute(kC1a, cudaFuncAttributeMaxDynamicSharedMemorySize, smC);
    cudaFuncSetAttribute(kE,   cudaFuncAttributeMaxDynamicSharedMemorySize, smE);

    kW<<<(384*96 + 255)/256, 256>>>(ipw, xpw, opw);
    kA<<<NB*144, 256, smA>>>(x);
    int nbB = (NB*96*48*24 + 255)/256;
    kB<<<nbB, 256>>>(cw, cb);
    kC1a<<<NB*KK*(LL/TLC), 256, smC>>>();
    kC1b<<<NB*KK*(LL/PXB), 256>>>(dtw, dtb);
    kD1<<<NB*KK*NSEG, 192>>>(alog);
    int nGrpT = NB*KK*GRP*DS*DI;
    kD2a<<<(nGrpT + 255)/256, 256>>>(alog);
    kD2b<<<(NB*KK*DS*DI + 255)/256, 256>>>(alog);
    kD2c<<<(nGrpT + 255)/256, 256>>>(alog);
    kD3<<<NB*KK*NSEG, 192>>>(alog, Dsv);
    kE<<<NB*(LL/64), 256, smE>>>(lng, lnb, x, out);
}

// round 16
// speedup vs baseline: 1.1755x; 1.1691x over previous
#include <cuda_runtime.h>
#include <cuda_fp16.h>
#include <mma.h>
#include <math.h>

using namespace nvcuda;

#define LL   9216
#define DI   192
#define DS   16
#define DR   6
#define KK   4
#define XD   38
#define NB   2
#define NSEG 192
#define CH   48
#define HH   96
#define WW   96
#define TLC  128
#define GRP  16
#define SEGPG (NSEG/GRP)
#define PXB  64
#define LDW  104      // kA weight row (halves)
#define LDX  72       // kA x row (halves)
#define LDC  200      // kC1a row (halves)
#define LDD  52       // kC1a sxd row (floats)

// ---------------- scratch ----------------
__device__ __half g_xi   [NB*LL*DI];
__device__ __half g_z    [NB*LL*DI];
__device__ __half g_xc   [NB*LL*DI];
__device__ __half g_delta[NB*KK*LL*DI];
__device__ __half g_y    [NB*KK*LL*DI];
__device__ float  g_bc   [NB*KK*LL*32];
__device__ float  g_dt6  [NB*KK*LL*8];
__device__ float  g_S    [NB*KK*NSEG*DS*DI];
__device__ float  g_dsm  [NB*KK*NSEG*DI];
__device__ float  g_h0   [NB*KK*NSEG*DS*DI];
__device__ float  g_Sg   [NB*KK*GRP*DS*DI];
__device__ float  g_dsmg [NB*KK*GRP*DI];
__device__ float  g_h0g  [NB*KK*GRP*DS*DI];
__device__ __half g_ipw_h[384*96];
__device__ __half g_xpw_h[KK*48*DI];
__device__ __half g_opw_h[96*200];

__constant__ float c_logn[DS] = {
    0.0f, 0.69314718f, 1.09861229f, 1.38629436f,
    1.60943791f, 1.79175947f, 1.94591015f, 2.07944154f,
    2.19722458f, 2.30258509f, 2.39789527f, 2.48490665f,
    2.56494936f, 2.63905733f, 2.70805020f, 2.77258872f
};

__device__ __forceinline__ float fast_softplus(float x){
    return fmaxf(x, 0.f) + __logf(1.f + __expf(-fabsf(x)));
}
__device__ __forceinline__ int pos_of(int k, int i){
    int t = (k >= 2) ? (LL - 1 - i) : i;
    if (k & 1){ int h = t % HH; int w = t / HH; return h*WW + w; }
    return t;
}
__device__ __forceinline__ bool row_fast(const float* arow){
    float a0 = arow[0];
    bool fast = true;
    #pragma unroll
    for (int n = 1; n < DS; n++)
        fast = fast && (fabsf(arow[n] - a0 - c_logn[n]) <= 2e-5f);
    return fast;
}
__device__ __forceinline__ int pstride_of(int k){
    return (k==0) ? 1 : (k==1) ? WW : (k==2) ? -1 : -WW;
}

// ---------------- kernel W: one-time fp16 weight conversion ----------------
__global__ void kW(const float* __restrict__ ipw, const float* __restrict__ xpw,
                   const float* __restrict__ opw){
    int t = blockIdx.x*256 + threadIdx.x;
    if (t < 384*96) g_ipw_h[t] = __float2half_rn(ipw[t]);
    if (t < KK*48*DI){
        int k = t / (48*DI);
        int r = t % (48*DI);
        g_xpw_h[t] = (r < XD*DI) ? __float2half_rn(xpw[k*XD*DI + r]) : __float2half_rn(0.f);
    }
    if (t < 96*200){
        int c = t/200, e = t%200;
        g_opw_h[t] = (e < DI) ? __float2half_rn(opw[c*DI + e]) : __float2half_rn(0.f);
    }
}

// ---------------- kernel A: in_proj via wmma (conflict-free padded smem) ----------------
__global__ void __launch_bounds__(256) kA(const float* __restrict__ x){
    extern __shared__ __align__(16) char smraw[];
    __half* swh = (__half*)smraw;        // [384][LDW]
    __half* sxh = swh + 384*LDW;         // [96][LDX]

    int tid = threadIdx.x;
    int b    = blockIdx.x / 144;
    int l0   = (blockIdx.x % 144) * 64;

    {
        const float4* src = (const float4*)g_ipw_h;   // rows of 12 float4
        float4* dst = (float4*)swh;                   // rows of 13 float4
        for (int i = tid; i < 384*12; i += 256)
            dst[(i/12)*13 + (i%12)] = src[i];
    }
    for (int i = tid; i < 96*64; i += 256){
        int e = i >> 6, j = i & 63;
        sxh[e*LDX + j] = __float2half_rn(x[(b*96 + e)*LL + l0 + j]);
    }
    __syncthreads();

    int wid = tid >> 5;
    wmma::fragment<wmma::accumulator,16,16,16,float> acc[3][4];
    #pragma unroll
    for (int i = 0; i < 3; i++)
        #pragma unroll
        for (int j = 0; j < 4; j++) wmma::fill_fragment(acc[i][j], 0.f);

    #pragma unroll
    for (int k = 0; k < 96; k += 16){
        wmma::fragment<wmma::matrix_a,16,16,16,__half,wmma::row_major> af[3];
        wmma::fragment<wmma::matrix_b,16,16,16,__half,wmma::row_major> bf[4];
        #pragma unroll
        for (int i = 0; i < 3; i++)
            wmma::load_matrix_sync(af[i], swh + (wid*48 + i*16)*LDW + k, LDW);
        #pragma unroll
        for (int j = 0; j < 4; j++)
            wmma::load_matrix_sync(bf[j], sxh + k*LDX + j*16, LDX);
        #pragma unroll
        for (int i = 0; i < 3; i++)
            #pragma unroll
            for (int j = 0; j < 4; j++)
                wmma::mma_sync(acc[i][j], af[i], bf[j], acc[i][j]);
    }

    #pragma unroll
    for (int i = 0; i < 3; i++){
        int orow = wid*48 + i*16;
        #pragma unroll
        for (int j = 0; j < 4; j++){
            wmma::fragment<wmma::accumulator,16,16,16,__half> hf;
            #pragma unroll
            for (int e = 0; e < hf.num_elements; e++)
                hf.x[e] = __float2half_rn(acc[i][j].x[e]);
            __half* dst;
            if (orow < DI) dst = g_xi + ((size_t)(b*LL + l0 + j*16))*DI + orow;
            else           dst = g_z  + ((size_t)(b*LL + l0 + j*16))*DI + (orow - DI);
            wmma::store_matrix_sync(dst, hf, DI, wmma::mem_col_major);
        }
    }
}

// ---------------- kernel B: depthwise 3x3 conv + SiLU ----------------
__global__ void __launch_bounds__(256) kB(const float* __restrict__ cw, const float* __restrict__ cb){
    __shared__ float scwT[9*DI];
    __shared__ float scb[DI];
    for (int i = threadIdx.x; i < DI*9; i += 256){
        int d = i/9, t = i%9; scwT[t*DI + d] = cw[i];
    }
    for (int i = threadIdx.x; i < DI; i += 256) scb[i] = cb[i];
    __syncthreads();

    int idx = blockIdx.x*256 + threadIdx.x;
    if (idx >= NB*96*48*24) return;
    int dg = idx % 24;
    int t  = idx / 24;
    int wp = t % 48;
    int h  = (t / 48) % 96;
    int b  = t / (48*96);
    int d  = dg*8;

    float acc0[8], acc1[8];
    #pragma unroll
    for (int i = 0; i < 8; i++){ acc0[i] = scb[d+i]; acc1[i] = scb[d+i]; }
    int wl = 2*wp - 1;
    bool hasL = (wl >= 0), hasR = (2*wp + 2 < WW);
    float4 zero4 = make_float4(0.f,0.f,0.f,0.f);

    #pragma unroll
    for (int ky = 0; ky < 3; ky++){
        int hh = h + ky - 1; if (hh < 0 || hh >= HH) continue;
        const __half* row = g_xi + ((size_t)b*LL + hh*WW)*DI + d;
        float4 q0 = hasL ? *(const float4*)(row + wl*DI)       : zero4;
        float4 q1 =        *(const float4*)(row + (2*wp)*DI);
        float4 q2 =        *(const float4*)(row + (2*wp+1)*DI);
        float4 q3 = hasR ? *(const float4*)(row + (2*wp+2)*DI) : zero4;
        float f0[8], f1[8], f2[8], f3[8];
        {
            __half2* p0 = (__half2*)&q0; __half2* p1 = (__half2*)&q1;
            __half2* p2 = (__half2*)&q2; __half2* p3 = (__half2*)&q3;
            #pragma unroll
            for (int j = 0; j < 4; j++){
                float2 a = __half22float2(p0[j]); f0[2*j] = a.x; f0[2*j+1] = a.y;
                float2 c = __half22float2(p1[j]); f1[2*j] = c.x; f1[2*j+1] = c.y;
                float2 e = __half22float2(p2[j]); f2[2*j] = e.x; f2[2*j+1] = e.y;
                float2 g = __half22float2(p3[j]); f3[2*j] = g.x; f3[2*j+1] = g.y;
            }
        }
        float wt[3][8];
        #pragma unroll
        for (int tap = 0; tap < 3; tap++){
            float4 a = *(const float4*)(scwT + (ky*3+tap)*DI + d);
            float4 bq = *(const float4*)(scwT + (ky*3+tap)*DI + d + 4);
            wt[tap][0]=a.x; wt[tap][1]=a.y; wt[tap][2]=a.z; wt[tap][3]=a.w;
            wt[tap][4]=bq.x; wt[tap][5]=bq.y; wt[tap][6]=bq.z; wt[tap][7]=bq.w;
        }
        #pragma unroll
        for (int i = 0; i < 8; i++){
            acc0[i] += wt[0][i]*f0[i] + wt[1][i]*f1[i] + wt[2][i]*f2[i];
            acc1[i] += wt[0][i]*f1[i] + wt[1][i]*f2[i] + wt[2][i]*f3[i];
        }
    }
    float4 o0, o1;
    __half2* o0h = (__half2*)&o0; __half2* o1h = (__half2*)&o1;
    #pragma unroll
    for (int j = 0; j < 4; j++){
        float s0a = acc0[2*j]   * (1.f/(1.f+__expf(-acc0[2*j])));
        float s0b = acc0[2*j+1] * (1.f/(1.f+__expf(-acc0[2*j+1])));
        float s1a = acc1[2*j]   * (1.f/(1.f+__expf(-acc1[2*j])));
        float s1b = acc1[2*j+1] * (1.f/(1.f+__expf(-acc1[2*j+1])));
        o0h[j] = __floats2half2_rn(s0a, s0b);
        o1h[j] = __floats2half2_rn(s1a, s1b);
    }
    __half* orow = g_xc + ((size_t)b*LL + h*WW)*DI + d;
    *(float4*)(orow + (2*wp)*DI)   = o0;
    *(float4*)(orow + (2*wp+1)*DI) = o1;
}

// ---------------- kernel C1a: gather + x_proj wmma (conflict-free) + B/C + dt6 ----------------
__global__ void __launch_bounds__(256) kC1a(){
    extern __shared__ __align__(16) char smraw[];
    __half* swph = (__half*)smraw;            // [48][LDC]
    __half* sxh  = swph + 48*LDC;             // [128][LDC]
    int*    spos = (int*)(sxh + TLC*LDC);     // [128]
    float*  sxd  = (float*)smraw;             // overlay: [128][LDD]
    int tid = threadIdx.x;
    int tile   = blockIdx.x;
    int ntile  = LL / TLC;
    int g  = tile / ntile;
    int i0 = (tile % ntile) * TLC;
    int b = g / KK, k = g % KK;

    {
        const float4* src = (const float4*)(g_xpw_h + k*48*DI);   // rows of 24 float4
        float4* dst = (float4*)swph;                               // rows of 25 float4
        for (int i = tid; i < 48*24; i += 256)
            dst[(i/24)*25 + (i%24)] = src[i];
    }
    if (tid < TLC) spos[tid] = pos_of(k, i0 + tid);
    __syncthreads();

    for (int i = tid; i < TLC*96; i += 256){
        int j = i / 96, dd = i % 96;
        *(__half2*)(sxh + j*LDC + 2*dd) =
            *(const __half2*)(g_xc + ((size_t)(b*LL + spos[j]))*DI + 2*dd);
    }
    __syncthreads();

    int wid = tid >> 5;
    wmma::fragment<wmma::accumulator,16,16,16,float> acc[3];
    #pragma unroll
    for (int i = 0; i < 3; i++) wmma::fill_fragment(acc[i], 0.f);
    #pragma unroll
    for (int k0 = 0; k0 < DI; k0 += 16){
        wmma::fragment<wmma::matrix_a,16,16,16,__half,wmma::row_major> af;
        wmma::fragment<wmma::matrix_b,16,16,16,__half,wmma::col_major> bf;
        wmma::load_matrix_sync(bf, sxh + (wid*16)*LDC + k0, LDC);
        #pragma unroll
        for (int i = 0; i < 3; i++){
            wmma::load_matrix_sync(af, swph + (i*16)*LDC + k0, LDC);
            wmma::mma_sync(acc[i], af, bf, acc[i]);
        }
    }
    __syncthreads();
    #pragma unroll
    for (int i = 0; i < 3; i++)
        wmma::store_matrix_sync(sxd + (wid*16)*LDD + i*16, acc[i], LDD, wmma::mem_col_major);
    __syncthreads();

    for (int o = tid; o < TLC*32; o += 256){
        int j = o >> 5, c = o & 31;
        g_bc[((size_t)g*LL + i0 + j)*32 + c] = sxd[j*LDD + 6 + c];
    }
    for (int o = tid; o < TLC*8; o += 256){
        int j = o >> 3, r = o & 7;
        g_dt6[((size_t)g*LL + i0 + j)*8 + r] = (r < DR) ? sxd[j*LDD + r] : 0.f;
    }
}

// ---------------- kernel C1b: dt proj + softplus, streaming ----------------
__global__ void __launch_bounds__(256) kC1b(const float* __restrict__ dtw,
                                            const float* __restrict__ dtb){
    __shared__ float sdw[DI*9];
    __shared__ float sdb[DI];
    __shared__ float sdt[PXB*8];
    int tid = threadIdx.x;
    int blk = blockIdx.x;
    int ntile = LL / PXB;
    int g  = blk / ntile;
    int i0 = (blk % ntile) * PXB;
    int k = g % KK;

    for (int i = tid; i < DI*DR; i += 256){
        int d = i/DR, r = i%DR; sdw[d*9 + r] = dtw[k*DI*DR + i];
    }
    for (int i = tid; i < DI; i += 256) sdb[i] = dtb[k*DI + i];
    {
        const float4* src = (const float4*)(g_dt6 + ((size_t)g*LL + i0)*8);
        float4* dst = (float4*)sdt;
        for (int i = tid; i < PXB*2; i += 256) dst[i] = src[i];
    }
    __syncthreads();

    int d = (tid < DI) ? tid : tid - DI;
    int j = (tid < DI) ? 0 : 1;
    __half* dbase = g_delta + ((size_t)g*LL + i0)*DI;
    #pragma unroll 4
    for (int it = 0; it < PXB*DI/256; it++){
        const float* xd = sdt + j*8;
        const float* dw = sdw + d*9;
        float acc2 = sdb[d];
        #pragma unroll
        for (int r = 0; r < DR; r++) acc2 += xd[r]*dw[r];
        dbase[(size_t)j*DI + d] = __float2half_rn(fast_softplus(acc2));
        d += 64;
        if (d >= DI){ d -= DI; j += 2; } else j += 1;
    }
}

// scan step body (fast path): grouped power chain, depth 4
#define STEP_BODY_D1(s2, delta, u) { \
    dsum += (delta); \
    float du = (delta)*(u); \
    float e1 = __expf((delta)*Ar0); \
    float e2 = e1*e1, e4 = e2*e2, e8 = e4*e4, e12 = e8*e4; \
    const float4* Bp4 = (const float4*)(sB + (s2)*DS); \
    float4 B0=Bp4[0],B1=Bp4[1],B2=Bp4[2],B3=Bp4[3]; \
    float aq = e1; \
    h[0]=aq*h[0]+du*B0.x; aq*=e1; h[1]=aq*h[1]+du*B0.y; aq*=e1; h[2]=aq*h[2]+du*B0.z; aq*=e1; h[3]=aq*h[3]+du*B0.w; \
    float bq = e4*e1; \
    h[4]=bq*h[4]+du*B1.x; bq*=e1; h[5]=bq*h[5]+du*B1.y; bq*=e1; h[6]=bq*h[6]+du*B1.z; bq*=e1; h[7]=bq*h[7]+du*B1.w; \
    float cq = e8*e1; \
    h[8]=cq*h[8]+du*B2.x; cq*=e1; h[9]=cq*h[9]+du*B2.y; cq*=e1; h[10]=cq*h[10]+du*B2.z; cq*=e1; h[11]=cq*h[11]+du*B2.w; \
    float dq = e12*e1; \
    h[12]=dq*h[12]+du*B3.x; dq*=e1; h[13]=dq*h[13]+du*B3.y; dq*=e1; h[14]=dq*h[14]+du*B3.z; dq*=e1; h[15]=dq*h[15]+du*B3.w; \
}

// ---------------- kernel D1: per-segment partial scan ----------------
__global__ void __launch_bounds__(192) kD1(const float* __restrict__ A_logs){
    __shared__ float sB[CH*DS];
    int g   = blockIdx.x / NSEG;
    int seg = blockIdx.x % NSEG;
    int b = g / KK, k = g % KK;
    int d = threadIdx.x;
    int l0 = seg * CH;

    for (int i = threadIdx.x; i < CH*DS; i += 192){
        int ss = i >> 4, c = i & 15;
        sB[i] = g_bc[((size_t)g*LL + l0 + ss)*32 + c];
    }
    __syncthreads();

    const float* arow = A_logs + (k*DI + d)*DS;
    bool fast = row_fast(arow);
    float Ar0 = -expf(arow[0]);

    float h[DS];
    #pragma unroll
    for (int n = 0; n < DS; n++) h[n] = 0.f;
    float dsum = 0.f;

    int p0   = pos_of(k, l0);
    int pstr = pstride_of(k) * DI;
    const __half* dptr = g_delta + ((size_t)g*LL + l0)*DI + d;
    const __half* uptr = g_xc + ((size_t)b*LL + p0)*DI + d;

    if (fast){
        for (int c0 = 0; c0 < CH; c0 += 4){
            float dl[4], uu[4];
            #pragma unroll
            for (int j = 0; j < 4; j++){
                dl[j] = __half2float(dptr[(c0+j)*DI]);
                uu[j] = __half2float(uptr[(c0+j)*pstr]);
            }
            #pragma unroll
            for (int j = 0; j < 4; j++){
                STEP_BODY_D1(c0+j, dl[j], uu[j]);
            }
        }
    } else {
        float Ar[DS];
        #pragma unroll
        for (int n = 0; n < DS; n++) Ar[n] = -expf(arow[n]);
        for (int s2 = 0; s2 < CH; s2++){
            float delta = __half2float(dptr[s2*DI]);
            float u = __half2float(uptr[s2*pstr]);
            dsum += delta;
            float du = delta*u;
            const float* Bp = sB + s2*DS;
            #pragma unroll
            for (int n = 0; n < DS; n++){
                float e = __expf(delta*Ar[n]);
                h[n] = e*h[n] + du*Bp[n];
            }
        }
    }
    size_t sbase = (((size_t)g*NSEG + seg)*DS)*DI + d;
    #pragma unroll
    for (int n = 0; n < DS; n++) g_S[sbase + n*DI] = h[n];
    g_dsm[((size_t)g*NSEG + seg)*DI + d] = dsum;
}

// ---------------- kernel D2a: per-group partial ----------------
__global__ void kD2a(const float* __restrict__ A_logs){
    int t = blockIdx.x*blockDim.x + threadIdx.x;
    if (t >= NB*KK*GRP*DS*DI) return;
    int d   = t % DI;
    int n   = (t/DI) % DS;
    int grp = (t/(DI*DS)) % GRP;
    int g   = t/(DI*DS*GRP);
    int k = g % KK;
    float An = -expf(A_logs[(k*DI + d)*DS + n]);
    float h = 0.f, dtot = 0.f;
    size_t base0 = (size_t)g*NSEG + grp*SEGPG;
    for (int s = 0; s < SEGPG; s++){
        size_t base = base0 + s;
        float dsm = g_dsm[base*DI + d];
        h = __expf(An*dsm)*h + g_S[(base*DS + n)*DI + d];
        dtot += dsm;
    }
    size_t gb = (size_t)g*GRP + grp;
    g_Sg[(gb*DS + n)*DI + d] = h;
    if (n == 0) g_dsmg[gb*DI + d] = dtot;
}

// ---------------- kernel D2b: scan 16 groups serially ----------------
__global__ void kD2b(const float* __restrict__ A_logs){
    int t = blockIdx.x*blockDim.x + threadIdx.x;
    if (t >= NB*KK*DS*DI) return;
    int d = t % DI; int n = (t/DI) % DS; int g = t/(DI*DS);
    int k = g % KK;
    float An = -expf(A_logs[(k*DI + d)*DS + n]);
    float h = 0.f;
    for (int grp = 0; grp < GRP; grp++){
        size_t gb = (size_t)g*GRP + grp;
        g_h0g[(gb*DS + n)*DI + d] = h;
        h = __expf(An*g_dsmg[gb*DI + d])*h + g_Sg[(gb*DS + n)*DI + d];
    }
}

// ---------------- kernel D2c: within-group h0 emit ----------------
__global__ void kD2c(const float* __restrict__ A_logs){
    int t = blockIdx.x*blockDim.x + threadIdx.x;
    if (t >= NB*KK*GRP*DS*DI) return;
    int d   = t % DI;
    int n   = (t/DI) % DS;
    int grp = (t/(DI*DS)) % GRP;
    int g   = t/(DI*DS*GRP);
    int k = g % KK;
    float An = -expf(A_logs[(k*DI + d)*DS + n]);
    size_t gb = (size_t)g*GRP + grp;
    float h = g_h0g[(gb*DS + n)*DI + d];
    size_t base0 = (size_t)g*NSEG + grp*SEGPG;
    for (int s = 0; s < SEGPG; s++){
        size_t base = base0 + s;
        g_h0[(base*DS + n)*DI + d] = h;
        h = __expf(An*g_dsm[base*DI + d])*h + g_S[(base*DS + n)*DI + d];
    }
}

#define STEP_BODY_D3(s2, delta, u) { \
    float du = (delta)*(u); \
    float e1 = __expf((delta)*Ar0); \
    float e2 = e1*e1, e4 = e2*e2, e8 = e4*e4, e12 = e8*e4; \
    const float4* P4 = (const float4*)(sBC + (s2)*32); \
    float4 B0=P4[0],B1=P4[1],B2=P4[2],B3=P4[3]; \
    float4 C0=P4[4],C1=P4[5],C2=P4[6],C3=P4[7]; \
    float y = 0.f; \
    float aq = e1; \
    h[0]=aq*h[0]+du*B0.x; y+=h[0]*C0.x; aq*=e1; h[1]=aq*h[1]+du*B0.y; y+=h[1]*C0.y; aq*=e1; \
    h[2]=aq*h[2]+du*B0.z; y+=h[2]*C0.z; aq*=e1; h[3]=aq*h[3]+du*B0.w; y+=h[3]*C0.w; \
    float bq = e4*e1; \
    h[4]=bq*h[4]+du*B1.x; y+=h[4]*C1.x; bq*=e1; h[5]=bq*h[5]+du*B1.y; y+=h[5]*C1.y; bq*=e1; \
    h[6]=bq*h[6]+du*B1.z; y+=h[6]*C1.z; bq*=e1; h[7]=bq*h[7]+du*B1.w; y+=h[7]*C1.w; \
    float cq = e8*e1; \
    h[8]=cq*h[8]+du*B2.x; y+=h[8]*C2.x; cq*=e1; h[9]=cq*h[9]+du*B2.y; y+=h[9]*C2.y; cq*=e1; \
    h[10]=cq*h[10]+du*B2.z; y+=h[10]*C2.z; cq*=e1; h[11]=cq*h[11]+du*B2.w; y+=h[11]*C2.w; \
    float dq = e12*e1; \
    h[12]=dq*h[12]+du*B3.x; y+=h[12]*C3.x; dq*=e1; h[13]=dq*h[13]+du*B3.y; y+=h[13]*C3.y; dq*=e1; \
    h[14]=dq*h[14]+du*B3.z; y+=h[14]*C3.z; dq*=e1; h[15]=dq*h[15]+du*B3.w; y+=h[15]*C3.w; \
    yptr[(s2)*DI] = __float2half_rn(y + Dval*(u)); \
}

// ---------------- kernel D3: full scan, emit y ----------------
__global__ void __launch_bounds__(192) kD3(const float* __restrict__ A_logs,
                                           const float* __restrict__ Dsv){
    __shared__ float sBC[CH*32];
    int g   = blockIdx.x / NSEG;
    int seg = blockIdx.x % NSEG;
    int b = g / KK, k = g % KK;
    int d = threadIdx.x;
    int l0 = seg * CH;

    {
        const float4* src = (const float4*)(g_bc + ((size_t)g*LL + l0)*32);
        float4* dst = (float4*)sBC;
        for (int i = threadIdx.x; i < CH*8; i += 192) dst[i] = src[i];
    }
    __syncthreads();

    const float* arow = A_logs + (k*DI + d)*DS;
    bool fast = row_fast(arow);
    float Ar0 = -expf(arow[0]);

    float h[DS];
    size_t hbase = (((size_t)g*NSEG + seg)*DS)*DI + d;
    #pragma unroll
    for (int n = 0; n < DS; n++) h[n] = g_h0[hbase + n*DI];
    float Dval = Dsv[k*DI + d];

    int p0   = pos_of(k, l0);
    int pstr = pstride_of(k) * DI;
    const __half* dptr = g_delta + ((size_t)g*LL + l0)*DI + d;
    const __half* uptr = g_xc + ((size_t)b*LL + p0)*DI + d;
    __half* yptr = g_y + ((size_t)g*LL + l0)*DI + d;

    if (fast){
        for (int c0 = 0; c0 < CH; c0 += 4){
            float dl[4], uu[4];
            #pragma unroll
            for (int j = 0; j < 4; j++){
                dl[j] = __half2float(dptr[(c0+j)*DI]);
                uu[j] = __half2float(uptr[(c0+j)*pstr]);
            }
            #pragma unroll
            for (int j = 0; j < 4; j++){
                STEP_BODY_D3(c0+j, dl[j], uu[j]);
            }
        }
    } else {
        float Ar[DS];
        #pragma unroll
        for (int n = 0; n < DS; n++) Ar[n] = -expf(arow[n]);
        for (int s2 = 0; s2 < CH; s2++){
            float delta = __half2float(dptr[s2*DI]);
            float u = __half2float(uptr[s2*pstr]);
            float du = delta*u;
            const float* Bp = sBC + s2*32;
            const float* Cp = Bp + 16;
            float y = 0.f;
            #pragma unroll
            for (int n = 0; n < DS; n++){
                float e = __expf(delta*Ar[n]);
                h[n] = e*h[n] + du*Bp[n];
                y += h[n]*Cp[n];
            }
            yptr[s2*DI] = __float2half_rn(y + Dval*u);
        }
    }
}

// ---------------- kernel E: merge + LN + gate + wmma out_proj + residual ----------------
__global__ void __launch_bounds__(256) kE(const float* __restrict__ lng,
                                          const float* __restrict__ lnb,
                                          const float* __restrict__ x,
                                          float* __restrict__ out){
    extern __shared__ __align__(16) char smraw[];
    __half* swh  = (__half*)smraw;           // [96][200]
    __half* syoh = swh + 96*200;             // [64][200]
    float*  slg  = (float*)(syoh + 64*200);  // [192]
    float*  slb  = slg + DI;                 // [192]
    float*  sout = (float*)syoh;             // reused after GEMM: [96][64]

    int tid = threadIdx.x;
    int b  = blockIdx.x / (LL/64);
    int p0 = (blockIdx.x % (LL/64)) * 64;

    {
        const float4* src = (const float4*)g_opw_h;
        float4* dst = (float4*)swh;
        for (int i = tid; i < 96*200/8; i += 256) dst[i] = src[i];
    }
    for (int i = tid; i < DI; i += 256){ slg[i] = lng[i]; slb[i] = lnb[i]; }
    for (int i = tid; i < 64*4; i += 256){
        int j = i/4, e = 192 + (i%4)*2;
        *(__half2*)(syoh + j*200 + e) = __floats2half2_rn(0.f, 0.f);
    }
    __syncthreads();

    int lane = tid & 31, wrp = tid >> 5;

    for (int jj = 0; jj < 8; jj++){
        int j = wrp*8 + jj;
        int p = p0 + j;
        int ph = p / WW, pw = p % WW;
        int i1 = pw*HH + ph;
        float val[6];
        #pragma unroll
        for (int i = 0; i < 6; i++){
            int d = lane + 32*i;
            val[i] = __half2float(g_y[(((size_t)(b*KK + 0))*LL + p)*DI + d])
                   + __half2float(g_y[(((size_t)(b*KK + 2))*LL + (LL-1-p))*DI + d])
                   + __half2float(g_y[(((size_t)(b*KK + 1))*LL + i1)*DI + d])
                   + __half2float(g_y[(((size_t)(b*KK + 3))*LL + (LL-1-i1))*DI + d]);
        }
        float s1 = 0.f, s2 = 0.f;
        #pragma unroll
        for (int i = 0; i < 6; i++){ s1 += val[i]; s2 += val[i]*val[i]; }
        #pragma unroll
        for (int off = 16; off; off >>= 1){
            s1 += __shfl_xor_sync(0xffffffffu, s1, off);
            s2 += __shfl_xor_sync(0xffffffffu, s2, off);
        }
        float mu  = s1 * (1.f/192.f);
        float var = s2 * (1.f/192.f) - mu*mu;
        float inv = rsqrtf(var + 1e-5f);
        #pragma unroll
        for (int i = 0; i < 6; i++){
            int d = lane + 32*i;
            float yo = (val[i] - mu)*inv*slg[d] + slb[d];
            float zv = __half2float(g_z[((size_t)b*LL + p)*DI + d]);
            yo *= zv * (1.f / (1.f + __expf(-zv)));
            syoh[j*200 + d] = __float2half_rn(yo);
        }
    }
    __syncthreads();

    wmma::fragment<wmma::accumulator,16,16,16,float> acc[4];
    int wid = tid >> 5;
    if (wid < 6){
        #pragma unroll
        for (int j = 0; j < 4; j++) wmma::fill_fragment(acc[j], 0.f);
        #pragma unroll
        for (int k0 = 0; k0 < DI; k0 += 16){
            wmma::fragment<wmma::matrix_a,16,16,16,__half,wmma::row_major> af;
            wmma::load_matrix_sync(af, swh + (wid*16)*200 + k0, 200);
            #pragma unroll
            for (int j = 0; j < 4; j++){
                wmma::fragment<wmma::matrix_b,16,16,16,__half,wmma::col_major> bf;
                wmma::load_matrix_sync(bf, syoh + (j*16)*200 + k0, 200);
                wmma::mma_sync(acc[j], af, bf, acc[j]);
            }
        }
    }
    __syncthreads();
    if (wid < 6){
        #pragma unroll
        for (int j = 0; j < 4; j++)
            wmma::store_matrix_sync(sout + (wid*16)*64 + j*16, acc[j], 64, wmma::mem_row_major);
    }
    __syncthreads();
    for (int idx = tid; idx < 96*64; idx += 256){
        int c = idx >> 6, jx = idx & 63;
        size_t go = ((size_t)b*96 + c)*LL + p0 + jx;
        out[go] = sout[idx] + x[go];
    }
}

// ---------------- launch ----------------
extern "C" void kernel_launch(void* const* d_in, const int* in_sizes, int n_in,
                              void* d_out, int out_size){
    const float* x    = (const float*)d_in[0];
    const float* ipw  = (const float*)d_in[1];
    const float* cw   = (const float*)d_in[2];
    const float* cb   = (const float*)d_in[3];
    const float* xpw  = (const float*)d_in[4];
    const float* dtw  = (const float*)d_in[5];
    const float* dtb  = (const float*)d_in[6];
    const float* alog = (const float*)d_in[7];
    const float* Dsv  = (const float*)d_in[8];
    const float* lng  = (const float*)d_in[9];
    const float* lnb  = (const float*)d_in[10];
    const float* opw  = (const float*)d_in[11];
    float* out = (float*)d_out;

    int smA = (384*LDW + 96*LDX)*2;
    int smC = (48*LDC + TLC*LDC)*2 + TLC*4;
    int smE = (96*200 + 64*200)*2 + (DI + DI)*4;
    cudaFuncSetAttribute(kA,   cudaFuncAttributeMaxDynamicSharedMemorySize, smA);
    cudaFuncSetAttribute(kC1a, cudaFuncAttributeMaxDynamicSharedMemorySize, smC);
    cudaFuncSetAttribute(kE,   cudaFuncAttributeMaxDynamicSharedMemorySize, smE);

    kW<<<(384*96 + 255)/256, 256>>>(ipw, xpw, opw);
    kA<<<NB*144, 256, smA>>>(x);
    int nbB = (NB*96*48*24 + 255)/256;
    kB<<<nbB, 256>>>(cw, cb);
    kC1a<<<NB*KK*(LL/TLC), 256, smC>>>();
    kC1b<<<NB*KK*(LL/PXB), 256>>>(dtw, dtb);
    kD1<<<NB*KK*NSEG, 192>>>(alog);
    int nGrpT = NB*KK*GRP*DS*DI;
    kD2a<<<(nGrpT + 255)/256, 256>>>(alog);
    kD2b<<<(NB*KK*DS*DI + 255)/256, 256>>>(alog);
    kD2c<<<(nGrpT + 255)/256, 256>>>(alog);
    kD3<<<NB*KK*NSEG, 192>>>(alog, Dsv);
    kE<<<NB*(LL/64), 256, smE>>>(lng, lnb, x, out);
}